// round 9
// baseline (speedup 1.0000x reference)
#include <cuda_runtime.h>
#include <cuda_bf16.h>
#include <cstdint>

#define NTOK 32768
#define DDIM 128
#define KHEADS 16

// ---------------- scratch (__device__ globals; no runtime allocation) ----------------
// X and W tiles are stored PRE-SWIZZLED (32B-unit XOR with row&7) so that flat
// cp.async.bulk copies land directly in an ldmatrix-conflict-free smem layout.
static __device__ __align__(16) __nv_bfloat16 g_Xb1[NTOK * DDIM];
static __device__ __align__(16) __nv_bfloat16 g_Xb2[NTOK * DDIM];
static __device__ __align__(16) __nv_bfloat16 g_Wb1[KHEADS * DDIM * DDIM]; // [k][e][d] W^T, swizzled
static __device__ __align__(16) __nv_bfloat16 g_Wb2[KHEADS * DDIM * DDIM];
static __device__ __align__(16) float g_P2[KHEADS * NTOK];                 // part2 + bias, fp32

// ---------------- helpers ----------------
__device__ __forceinline__ uint32_t smem_u32(const void* p) {
    uint32_t a;
    asm("{ .reg .u64 t; cvta.to.shared.u64 t, %1; cvt.u32.u64 %0, t; }" : "=r"(a) : "l"(p));
    return a;
}

#define MBARRIER_INIT(mbar, count) \
    asm volatile("mbarrier.init.shared.b64 [%0], %1;" :: "r"((uint32_t)(mbar)), "r"((uint32_t)(count)) : "memory")
#define MBARRIER_EXPECT_TX(mbar, bytes) \
    asm volatile("mbarrier.arrive.expect_tx.shared.b64 _, [%0], %1;" \
                 :: "r"((uint32_t)(mbar)), "r"((uint32_t)(bytes)) : "memory")
#define MBARRIER_WAIT_PARITY(mbar, parity) do { \
    uint32_t _m = (uint32_t)(mbar); uint32_t _p = (uint32_t)(parity); uint32_t _done; \
    asm volatile("{\n\t.reg .pred p;\n\t" \
        "mbarrier.try_wait.parity.acquire.cta.shared::cta.b64 p, [%1], %2;\n\t" \
        "selp.b32 %0, 1, 0, p;\n\t}" : "=r"(_done) : "r"(_m), "r"(_p) : "memory"); \
    if (!_done) { \
        asm volatile("{\n\t.reg .pred P1;\n\t" \
            "WL_%=:\n\t" \
            "mbarrier.try_wait.parity.acquire.cta.shared::cta.b64 P1, [%0], %1, 0x989680;\n\t" \
            "@P1 bra.uni WD_%=;\n\t" \
            "bra.uni WL_%=;\n\t" \
            "WD_%=:\n\t}" :: "r"(_m), "r"(_p) : "memory"); \
    } \
} while (0)

// Bulk DMA copy: global -> shared, completion via mbarrier complete_tx.
#define CP_BULK(dst_smem, src_gmem, bytes, mbar) \
    asm volatile("cp.async.bulk.shared::cluster.global.mbarrier::complete_tx::bytes " \
                 "[%0], [%1], %2, [%3];" \
                 :: "r"((uint32_t)(dst_smem)), "l"(src_gmem), "r"((uint32_t)(bytes)), \
                    "r"((uint32_t)(mbar)) : "memory")
#define FENCE_PROXY_ASYNC() asm volatile("fence.proxy.async.shared::cta;" ::: "memory")

#define LDSM_X4(r0, r1, r2, r3, addr) \
    asm volatile("ldmatrix.sync.aligned.m8n8.x4.shared.b16 {%0,%1,%2,%3}, [%4];" \
                 : "=r"(r0), "=r"(r1), "=r"(r2), "=r"(r3) : "r"(addr))
#define LDSM_X2(r0, r1, addr) \
    asm volatile("ldmatrix.sync.aligned.m8n8.x2.shared.b16 {%0,%1}, [%2];" \
                 : "=r"(r0), "=r"(r1) : "r"(addr))

#define MMA_BF16(c, a, b0v, b1v) \
    asm volatile("mma.sync.aligned.m16n8k16.row.col.f32.bf16.bf16.f32 " \
                 "{%0,%1,%2,%3}, {%4,%5,%6,%7}, {%8,%9}, {%0,%1,%2,%3};" \
                 : "+f"((c)[0]), "+f"((c)[1]), "+f"((c)[2]), "+f"((c)[3]) \
                 : "r"((a)[0]), "r"((a)[1]), "r"((a)[2]), "r"((a)[3]), \
                   "r"(b0v), "r"(b1v))

// ---------------- smem layout of main kernel (all tiles flat 256B rows, pre-swizzled) ----
#define SM_X1   0
#define SM_X2   32768
#define SM_W    65536              // + buf*65536 ; W1 at +0, W2 at +32768
#define SM_RED  196608             // 128 rows x 3 floats
#define SM_MBAR 198144             // mbars: X @+0, W0 @+8, W1 @+16
#define SM_TOT  198208

// ================= fused prep =================
// Blocks [0, 512): convert x -> bf16 (swizzled) + part2 (fp32, V amortized 8x).
// Blocks [512, 1024): W transpose+convert -> swizzled [k][e][d] bf16.
__global__ void __launch_bounds__(256) k_prep(const float* __restrict__ x1,
                                              const float* __restrict__ x2,
                                              const float* __restrict__ W1,
                                              const float* __restrict__ W2,
                                              const float* __restrict__ V,
                                              const float* __restrict__ b) {
    __shared__ float t[32][33];
    int bid = blockIdx.x;
    if (bid < 512) {
        int w = threadIdx.x >> 5, lane = threadIdx.x & 31;
        int row0 = (bid * 8 + w) * 8;

        float4 xv1[8], xv2[8];
        #pragma unroll
        for (int r = 0; r < 8; r++) {
            int rr = row0 + r;
            xv1[r] = __ldg(reinterpret_cast<const float4*>(x1 + (size_t)rr * DDIM) + lane);
            xv2[r] = __ldg(reinterpret_cast<const float4*>(x2 + (size_t)rr * DDIM) + lane);
            uint32_t off = ((uint32_t)(lane * 8)) ^ ((uint32_t)(rr & 7) << 5);  // 32B-unit swizzle
            {
                __nv_bfloat162 lo = __floats2bfloat162_rn(xv1[r].x, xv1[r].y);
                __nv_bfloat162 hi = __floats2bfloat162_rn(xv1[r].z, xv1[r].w);
                uint2 pk;
                pk.x = *reinterpret_cast<uint32_t*>(&lo);
                pk.y = *reinterpret_cast<uint32_t*>(&hi);
                *reinterpret_cast<uint2*>(reinterpret_cast<char*>(g_Xb1) + (size_t)rr * 256 + off) = pk;
            }
            {
                __nv_bfloat162 lo = __floats2bfloat162_rn(xv2[r].x, xv2[r].y);
                __nv_bfloat162 hi = __floats2bfloat162_rn(xv2[r].z, xv2[r].w);
                uint2 pk;
                pk.x = *reinterpret_cast<uint32_t*>(&lo);
                pk.y = *reinterpret_cast<uint32_t*>(&hi);
                *reinterpret_cast<uint2*>(reinterpret_cast<char*>(g_Xb2) + (size_t)rr * 256 + off) = pk;
            }
        }

        #pragma unroll
        for (int k = 0; k < KHEADS; k++) {
            float4 w1 = __ldg(reinterpret_cast<const float4*>(V + k * 256) + lane);
            float4 w2 = __ldg(reinterpret_cast<const float4*>(V + k * 256 + 128) + lane);
            float a[8];
            #pragma unroll
            for (int r = 0; r < 8; r++) {
                float s = xv1[r].x * w1.x;
                s = fmaf(xv1[r].y, w1.y, s);
                s = fmaf(xv1[r].z, w1.z, s);
                s = fmaf(xv1[r].w, w1.w, s);
                s = fmaf(xv2[r].x, w2.x, s);
                s = fmaf(xv2[r].y, w2.y, s);
                s = fmaf(xv2[r].z, w2.z, s);
                s = fmaf(xv2[r].w, w2.w, s);
                a[r] = s;
            }
            #pragma unroll
            for (int m = 16; m >= 1; m >>= 1) {
                #pragma unroll
                for (int r = 0; r < 8; r++) a[r] += __shfl_xor_sync(0xFFFFFFFFu, a[r], m);
            }
            if (lane < 8) g_P2[k * NTOK + row0 + lane] = a[lane] + __ldg(&b[k]);
        }
    } else {
        int idx = bid - 512;
        int k = idx >> 5;
        int rem = idx & 31;
        int dtx = rem & 3;
        int y = (rem >> 2) & 7;
        int which = y >> 2;
        int ety = y & 3;
        int tx = threadIdx.x & 31, ty = threadIdx.x >> 5;
        const float* src = which ? W2 : W1;
        char* dst = reinterpret_cast<char*>(which ? g_Wb2 : g_Wb1);
        #pragma unroll
        for (int r = 0; r < 32; r += 8) {
            int d = dtx * 32 + ty + r;
            int e = ety * 32 + tx;
            t[ty + r][tx] = src[k * 16384 + d * 128 + e];
        }
        __syncthreads();
        #pragma unroll
        for (int r = 0; r < 32; r += 8) {
            int e = ety * 32 + ty + r;
            int d = dtx * 32 + tx;
            uint32_t off = ((uint32_t)(d * 2)) ^ ((uint32_t)(e & 7) << 5);
            *reinterpret_cast<__nv_bfloat16*>(dst + (size_t)k * 32768 + (size_t)e * 256 + off) =
                __float2bfloat16(t[tx][ty + r]);
        }
    }
}

// ================= main HMMA kernel =================
// 256 CTAs x 128 rows; 512 threads (16 warps). Warp (r=wid&7, c=wid>>3):
// rows [r*16, r*16+16), e-cols [c*64, c*64+64). A-frags resident across all heads.
// W staged per head via cp.async.bulk DMA (zero per-warp issue cost), double-buffered.
__global__ void __launch_bounds__(512, 1) k_main(float* __restrict__ out) {
    extern __shared__ char smem[];
    uint32_t sb = smem_u32(smem);
    int tid = threadIdx.x, wid = tid >> 5, lid = tid & 31;
    int n0 = blockIdx.x * 128;
    int r = wid & 7, c = wid >> 3;
    uint32_t mb = sb + SM_MBAR;

    if (tid == 0) {
        MBARRIER_INIT(mb + 0, 1);
        MBARRIER_INIT(mb + 8, 1);
        MBARRIER_INIT(mb + 16, 1);
    }
    __syncthreads();

    if (tid == 0) {
        MBARRIER_EXPECT_TX(mb + 0, 65536);
        CP_BULK(sb + SM_X1, reinterpret_cast<const char*>(g_Xb1) + (size_t)blockIdx.x * 32768, 32768, mb + 0);
        CP_BULK(sb + SM_X2, reinterpret_cast<const char*>(g_Xb2) + (size_t)blockIdx.x * 32768, 32768, mb + 0);
        MBARRIER_EXPECT_TX(mb + 8, 65536);
        CP_BULK(sb + SM_W,         reinterpret_cast<const char*>(g_Wb1), 32768, mb + 8);
        CP_BULK(sb + SM_W + 32768, reinterpret_cast<const char*>(g_Wb2), 32768, mb + 8);
        MBARRIER_EXPECT_TX(mb + 16, 65536);
        CP_BULK(sb + SM_W + 65536,         reinterpret_cast<const char*>(g_Wb1) + 32768, 32768, mb + 16);
        CP_BULK(sb + SM_W + 65536 + 32768, reinterpret_cast<const char*>(g_Wb2) + 32768, 32768, mb + 16);
    }

    // wait X, load A fragments (resident for all 16 heads)
    MBARRIER_WAIT_PARITY(mb + 0, 0);
    int l15 = lid & 15, lr = l15 & 7;
    uint32_t a1f[8][4], a2f[8][4];
    {
        uint32_t abase = (uint32_t)(r * 16 + l15) * 256 + (uint32_t)(lid >> 4) * 16;
        #pragma unroll
        for (int s = 0; s < 8; s++) {
            uint32_t ao = abase + (uint32_t)((s ^ lr) << 5);
            LDSM_X4(a1f[s][0], a1f[s][1], a1f[s][2], a1f[s][3], sb + SM_X1 + ao);
            LDSM_X4(a2f[s][0], a2f[s][1], a2f[s][2], a2f[s][3], sb + SM_X2 + ao);
        }
    }

    uint32_t bbase = (uint32_t)(c * 64 + lr) * 256 + (uint32_t)(l15 >> 3) * 16;
    float* red = reinterpret_cast<float*>(smem + SM_RED);
    uint32_t ph0 = 0, ph1 = 0;
    int g = lid >> 2;
    bool leader = (lid & 3) == 0;

    for (int k = 0; k < KHEADS; k++) {
        int buf = k & 1;
        if (buf == 0) { MBARRIER_WAIT_PARITY(mb + 8, ph0);  ph0 ^= 1; }
        else          { MBARRIER_WAIT_PARITY(mb + 16, ph1); ph1 ^= 1; }

        // prefetch part2 (hides L2 latency under the MMA loop)
        float p2v[2] = {0.f, 0.f};
        if (c == 0 && leader) {
            p2v[0] = g_P2[k * NTOK + n0 + r * 16 + g];
            p2v[1] = g_P2[k * NTOK + n0 + r * 16 + 8 + g];
        }

        uint32_t wbase = sb + SM_W + (uint32_t)buf * 65536;
        uint32_t b1 = wbase + bbase;
        uint32_t b2 = b1 + 32768;

        float dot[2] = {0, 0}, s1s[2] = {0, 0}, s2s[2] = {0, 0};

        #pragma unroll
        for (int ecg = 0; ecg < 4; ecg++) {
            float c1[2][4] = {{0, 0, 0, 0}, {0, 0, 0, 0}};
            float c2[2][4] = {{0, 0, 0, 0}, {0, 0, 0, 0}};
            #pragma unroll
            for (int s = 0; s < 8; s++) {
                uint32_t so = (uint32_t)((s ^ lr) << 5);
                #pragma unroll
                for (int ec = 0; ec < 2; ec++) {
                    uint32_t po = (uint32_t)((ecg * 2 + ec) * 2048) + so;
                    uint32_t u0, u1, v0, v1;
                    LDSM_X2(u0, u1, b1 + po);
                    LDSM_X2(v0, v1, b2 + po);
                    MMA_BF16(c1[ec], a1f[s], u0, u1);
                    MMA_BF16(c2[ec], a2f[s], v0, v1);
                }
            }
            #pragma unroll
            for (int ec = 0; ec < 2; ec++) {
                dot[0] = fmaf(c1[ec][0], c2[ec][0], dot[0]);
                dot[0] = fmaf(c1[ec][1], c2[ec][1], dot[0]);
                dot[1] = fmaf(c1[ec][2], c2[ec][2], dot[1]);
                dot[1] = fmaf(c1[ec][3], c2[ec][3], dot[1]);
                s1s[0] = fmaf(c1[ec][0], c1[ec][0], s1s[0]);
                s1s[0] = fmaf(c1[ec][1], c1[ec][1], s1s[0]);
                s1s[1] = fmaf(c1[ec][2], c1[ec][2], s1s[1]);
                s1s[1] = fmaf(c1[ec][3], c1[ec][3], s1s[1]);
                s2s[0] = fmaf(c2[ec][0], c2[ec][0], s2s[0]);
                s2s[0] = fmaf(c2[ec][1], c2[ec][1], s2s[0]);
                s2s[1] = fmaf(c2[ec][2], c2[ec][2], s2s[1]);
                s2s[1] = fmaf(c2[ec][3], c2[ec][3], s2s[1]);
            }
        }

        #pragma unroll
        for (int msk = 1; msk <= 2; msk <<= 1) {
            #pragma unroll
            for (int h = 0; h < 2; h++) {
                dot[h] += __shfl_xor_sync(0xFFFFFFFFu, dot[h], msk);
                s1s[h] += __shfl_xor_sync(0xFFFFFFFFu, s1s[h], msk);
                s2s[h] += __shfl_xor_sync(0xFFFFFFFFu, s2s[h], msk);
            }
        }

        if (c == 1 && leader) {
            #pragma unroll
            for (int h = 0; h < 2; h++) {
                int rr = r * 16 + h * 8 + g;
                red[rr * 3 + 0] = dot[h];
                red[rr * 3 + 1] = s1s[h];
                red[rr * 3 + 2] = s2s[h];
            }
        }
        __syncthreads();
        if (c == 0 && leader) {
            #pragma unroll
            for (int h = 0; h < 2; h++) {
                int rr = r * 16 + h * 8 + g;
                int n = n0 + rr;
                float D = dot[h] + red[rr * 3 + 0];
                float A = s1s[h] + red[rr * 3 + 1];
                float B = s2s[h] + red[rr * 3 + 2];
                float v = D / (fmaxf(sqrtf(A), 1e-8f) * fmaxf(sqrtf(B), 1e-8f)) + p2v[h];
                out[(size_t)n * KHEADS + k] = fmaxf(v, 0.f);
            }
        }
        __syncthreads();   // all reads of buf done (and red consumed) before refill

        if (tid == 0 && k + 2 < KHEADS) {
            FENCE_PROXY_ASYNC();
            uint32_t wm = mb + 8 + (uint32_t)buf * 8;
            MBARRIER_EXPECT_TX(wm, 65536);
            CP_BULK(sb + SM_W + (uint32_t)buf * 65536,
                    reinterpret_cast<const char*>(g_Wb1) + (size_t)(k + 2) * 32768, 32768, wm);
            CP_BULK(sb + SM_W + (uint32_t)buf * 65536 + 32768,
                    reinterpret_cast<const char*>(g_Wb2) + (size_t)(k + 2) * 32768, 32768, wm);
        }
    }
}

// ================= launch =================
extern "C" void kernel_launch(void* const* d_in, const int* in_sizes, int n_in,
                              void* d_out, int out_size) {
    const float* x1 = (const float*)d_in[0];
    const float* x2 = (const float*)d_in[1];
    const float* W1 = (const float*)d_in[2];
    const float* W2 = (const float*)d_in[3];
    const float* V  = (const float*)d_in[4];
    const float* b  = (const float*)d_in[5];
    float* out = (float*)d_out;

    k_prep<<<1024, 256>>>(x1, x2, W1, W2, V, b);

    cudaFuncSetAttribute(k_main, cudaFuncAttributeMaxDynamicSharedMemorySize, SM_TOT);
    k_main<<<NTOK / 128, 512, SM_TOT>>>(out);
}

// round 14
// speedup vs baseline: 1.5776x; 1.5776x over previous
#include <cuda_runtime.h>
#include <cuda_bf16.h>
#include <cstdint>

#define NTOK 32768
#define DDIM 128
#define KHEADS 16
#define NTILES 256            // NTOK / 128
#define NQ (NTILES * KHEADS)  // 4096 work quanta
#define NCTA 148

// ---------------- scratch: PADDED tiles (272B rows) for flat bulk-DMA staging ----------
// Row stride 272B => bank stride 16 mod 128 => conflict-free ldmatrix (proven in R5-R8).
#define ROWB   272
#define TILEB  (128 * ROWB)   // 34816 bytes per 128x128 bf16 tile
static __device__ __align__(16) char g_Xp1[NTILES * TILEB];           // x1 tiles, bf16 padded
static __device__ __align__(16) char g_Xp2[NTILES * TILEB];           // x2 tiles
static __device__ __align__(16) char g_Wp1[KHEADS * TILEB];           // W1^T [k][e][d] padded
static __device__ __align__(16) char g_Wp2[KHEADS * TILEB];           // W2^T
static __device__ __align__(16) float g_P2[KHEADS * NTOK];            // part2 + bias, fp32

// ---------------- helpers ----------------
__device__ __forceinline__ uint32_t smem_u32(const void* p) {
    uint32_t a;
    asm("{ .reg .u64 t; cvta.to.shared.u64 t, %1; cvt.u32.u64 %0, t; }" : "=r"(a) : "l"(p));
    return a;
}

#define MBARRIER_INIT(mbar, count) \
    asm volatile("mbarrier.init.shared.b64 [%0], %1;" :: "r"((uint32_t)(mbar)), "r"((uint32_t)(count)) : "memory")
#define MBARRIER_EXPECT_TX(mbar, bytes) \
    asm volatile("mbarrier.arrive.expect_tx.shared.b64 _, [%0], %1;" \
                 :: "r"((uint32_t)(mbar)), "r"((uint32_t)(bytes)) : "memory")
#define MBARRIER_WAIT_PARITY(mbar, parity) do { \
    uint32_t _m = (uint32_t)(mbar); uint32_t _p = (uint32_t)(parity); uint32_t _done; \
    asm volatile("{\n\t.reg .pred p;\n\t" \
        "mbarrier.try_wait.parity.acquire.cta.shared::cta.b64 p, [%1], %2;\n\t" \
        "selp.b32 %0, 1, 0, p;\n\t}" : "=r"(_done) : "r"(_m), "r"(_p) : "memory"); \
    if (!_done) { \
        asm volatile("{\n\t.reg .pred P1;\n\t" \
            "WL_%=:\n\t" \
            "mbarrier.try_wait.parity.acquire.cta.shared::cta.b64 P1, [%0], %1, 0x989680;\n\t" \
            "@P1 bra.uni WD_%=;\n\t" \
            "bra.uni WL_%=;\n\t" \
            "WD_%=:\n\t}" :: "r"(_m), "r"(_p) : "memory"); \
    } \
} while (0)

#define CP_BULK(dst_smem, src_gmem, bytes, mbar) \
    asm volatile("cp.async.bulk.shared::cluster.global.mbarrier::complete_tx::bytes " \
                 "[%0], [%1], %2, [%3];" \
                 :: "r"((uint32_t)(dst_smem)), "l"(src_gmem), "r"((uint32_t)(bytes)), \
                    "r"((uint32_t)(mbar)) : "memory")
#define FENCE_PROXY_ASYNC() asm volatile("fence.proxy.async.shared::cta;" ::: "memory")

#define LDSM_X4(r0, r1, r2, r3, addr) \
    asm volatile("ldmatrix.sync.aligned.m8n8.x4.shared.b16 {%0,%1,%2,%3}, [%4];" \
                 : "=r"(r0), "=r"(r1), "=r"(r2), "=r"(r3) : "r"(addr))
#define LDSM_X2(r0, r1, addr) \
    asm volatile("ldmatrix.sync.aligned.m8n8.x2.shared.b16 {%0,%1}, [%2];" \
                 : "=r"(r0), "=r"(r1) : "r"(addr))

#define MMA_BF16(c, a, b0v, b1v) \
    asm volatile("mma.sync.aligned.m16n8k16.row.col.f32.bf16.bf16.f32 " \
                 "{%0,%1,%2,%3}, {%4,%5,%6,%7}, {%8,%9}, {%0,%1,%2,%3};" \
                 : "+f"((c)[0]), "+f"((c)[1]), "+f"((c)[2]), "+f"((c)[3]) \
                 : "r"((a)[0]), "r"((a)[1]), "r"((a)[2]), "r"((a)[3]), \
                   "r"(b0v), "r"(b1v))

// ---------------- smem layout (main) ----------------
#define SM_X1   0
#define SM_X2   TILEB
#define SM_W    (2 * TILEB)               // buf b at + b*(2*TILEB); W1 at +0, W2 at +TILEB
#define SM_RED  (6 * TILEB)               // 128 rows x 3 floats
#define SM_MBAR (6 * TILEB + 1536)        // X @+0, W0 @+8, W1 @+16
#define SM_TOT  (6 * TILEB + 1536 + 32)   // 210464 B

// ================= fused prep =================
// Blocks [0, 1024): convert x -> bf16 padded tiles + part2 (fp32, warp-per-4-rows).
// Blocks [1024, 1536): W transpose+convert -> padded [k][e][d] bf16.
__global__ void __launch_bounds__(256) k_prep(const float* __restrict__ x1,
                                              const float* __restrict__ x2,
                                              const float* __restrict__ W1,
                                              const float* __restrict__ W2,
                                              const float* __restrict__ V,
                                              const float* __restrict__ b) {
    __shared__ float t[32][33];
    int bid = blockIdx.x;
    if (bid < 1024) {
        int w = threadIdx.x >> 5, lane = threadIdx.x & 31;
        int row0 = (bid * 8 + w) * 4;

        float4 xv1[4], xv2[4];
        #pragma unroll
        for (int r = 0; r < 4; r++) {
            int rr = row0 + r;
            xv1[r] = __ldg(reinterpret_cast<const float4*>(x1 + (size_t)rr * DDIM) + lane);
            xv2[r] = __ldg(reinterpret_cast<const float4*>(x2 + (size_t)rr * DDIM) + lane);
            // 4 fp32 -> 4 bf16 = 8 BYTES per lane: stride lane*8 (R13 bug was lane*16)
            size_t off = (size_t)(rr >> 7) * TILEB + (size_t)(rr & 127) * ROWB + (size_t)lane * 8;
            {
                __nv_bfloat162 lo = __floats2bfloat162_rn(xv1[r].x, xv1[r].y);
                __nv_bfloat162 hi = __floats2bfloat162_rn(xv1[r].z, xv1[r].w);
                uint2 pk;
                pk.x = *reinterpret_cast<uint32_t*>(&lo);
                pk.y = *reinterpret_cast<uint32_t*>(&hi);
                *reinterpret_cast<uint2*>(g_Xp1 + off) = pk;
            }
            {
                __nv_bfloat162 lo = __floats2bfloat162_rn(xv2[r].x, xv2[r].y);
                __nv_bfloat162 hi = __floats2bfloat162_rn(xv2[r].z, xv2[r].w);
                uint2 pk;
                pk.x = *reinterpret_cast<uint32_t*>(&lo);
                pk.y = *reinterpret_cast<uint32_t*>(&hi);
                *reinterpret_cast<uint2*>(g_Xp2 + off) = pk;
            }
        }

        #pragma unroll
        for (int k = 0; k < KHEADS; k++) {
            float4 w1 = __ldg(reinterpret_cast<const float4*>(V + k * 256) + lane);
            float4 w2 = __ldg(reinterpret_cast<const float4*>(V + k * 256 + 128) + lane);
            float a[4];
            #pragma unroll
            for (int r = 0; r < 4; r++) {
                float s = xv1[r].x * w1.x;
                s = fmaf(xv1[r].y, w1.y, s);
                s = fmaf(xv1[r].z, w1.z, s);
                s = fmaf(xv1[r].w, w1.w, s);
                s = fmaf(xv2[r].x, w2.x, s);
                s = fmaf(xv2[r].y, w2.y, s);
                s = fmaf(xv2[r].z, w2.z, s);
                s = fmaf(xv2[r].w, w2.w, s);
                a[r] = s;
            }
            // full butterfly -> each a[r] warp-uniform; lane i emits row i's value
            #pragma unroll
            for (int m = 16; m >= 1; m >>= 1) {
                #pragma unroll
                for (int r = 0; r < 4; r++) a[r] += __shfl_xor_sync(0xFFFFFFFFu, a[r], m);
            }
            if (lane < 4) g_P2[k * NTOK + row0 + lane] = a[lane] + __ldg(&b[k]);
        }
    } else {
        int idx = bid - 1024;
        int k = idx >> 5;
        int rem = idx & 31;
        int dtx = rem & 3;
        int y = (rem >> 2) & 7;
        int which = y >> 2;
        int ety = y & 3;
        int tx = threadIdx.x & 31, ty = threadIdx.x >> 5;
        const float* src = which ? W2 : W1;
        char* dst = which ? g_Wp2 : g_Wp1;
        #pragma unroll
        for (int r = 0; r < 32; r += 8) {
            int d = dtx * 32 + ty + r;
            int e = ety * 32 + tx;
            t[ty + r][tx] = src[k * 16384 + d * 128 + e];
        }
        __syncthreads();
        #pragma unroll
        for (int r = 0; r < 32; r += 8) {
            int e = ety * 32 + ty + r;
            int d = dtx * 32 + tx;
            *reinterpret_cast<__nv_bfloat16*>(dst + (size_t)k * TILEB + (size_t)e * ROWB + d * 2) =
                __float2bfloat16(t[tx][ty + r]);
        }
    }
}

// ================= persistent main HMMA kernel =================
// 148 CTAs x 512 threads. Quantum q in [0, 4096): tile t = q>>4, head k = q&15.
// CTA i owns quanta [i*NQ/NCTA, (i+1)*NQ/NCTA) -> wave-balanced (27-28 quanta each).
// X tile + A-frags reloaded only on tile change (2-3x per CTA); W double-buffered bulk-DMA.
__global__ void __launch_bounds__(512, 1) k_main(float* __restrict__ out) {
    extern __shared__ char smem[];
    uint32_t sb = smem_u32(smem);
    int tid = threadIdx.x, wid = tid >> 5, lid = tid & 31;
    int r = wid & 7, c = wid >> 3;
    uint32_t mb = sb + SM_MBAR;

    int q0 = (int)(((long)blockIdx.x * NQ) / NCTA);
    int q1 = (int)(((long)(blockIdx.x + 1) * NQ) / NCTA);

    if (tid == 0) {
        MBARRIER_INIT(mb + 0, 1);
        MBARRIER_INIT(mb + 8, 1);
        MBARRIER_INIT(mb + 16, 1);
    }
    __syncthreads();

    // prologue: W for first two quanta
    if (tid == 0) {
        int ka = q0 & 15;
        MBARRIER_EXPECT_TX(mb + 8, 2 * TILEB);
        CP_BULK(sb + SM_W,         g_Wp1 + (size_t)ka * TILEB, TILEB, mb + 8);
        CP_BULK(sb + SM_W + TILEB, g_Wp2 + (size_t)ka * TILEB, TILEB, mb + 8);
        if (q0 + 1 < q1) {
            int kb = (q0 + 1) & 15;
            MBARRIER_EXPECT_TX(mb + 16, 2 * TILEB);
            CP_BULK(sb + SM_W + 2 * TILEB,         g_Wp1 + (size_t)kb * TILEB, TILEB, mb + 16);
            CP_BULK(sb + SM_W + 2 * TILEB + TILEB, g_Wp2 + (size_t)kb * TILEB, TILEB, mb + 16);
        }
    }

    int l15 = lid & 15;
    uint32_t a1f[8][4], a2f[8][4];
    uint32_t abase = (uint32_t)(r * 16 + l15) * ROWB + (uint32_t)(lid >> 4) * 16;
    uint32_t bbase = (uint32_t)(l15 & 7) * ROWB + (uint32_t)(l15 >> 3) * 16
                   + (uint32_t)c * 64 * ROWB;
    float* red = reinterpret_cast<float*>(smem + SM_RED);
    int g = lid >> 2;
    bool leader = (lid & 3) == 0;

    int cur_t = -1;
    uint32_t xph = 0, wph0 = 0, wph1 = 0;

    for (int q = q0; q < q1; q++) {
        int t = q >> 4, k = q & 15;
        int buf = (q - q0) & 1;

        // --- stage X tile on tile change (all warps aligned here) ---
        if (t != cur_t) {
            cur_t = t;
            if (tid == 0) {
                FENCE_PROXY_ASYNC();
                MBARRIER_EXPECT_TX(mb + 0, 2 * TILEB);
                CP_BULK(sb + SM_X1, g_Xp1 + (size_t)t * TILEB, TILEB, mb + 0);
                CP_BULK(sb + SM_X2, g_Xp2 + (size_t)t * TILEB, TILEB, mb + 0);
            }
            MBARRIER_WAIT_PARITY(mb + 0, xph);
            xph ^= 1;
            #pragma unroll
            for (int s = 0; s < 8; s++) {
                LDSM_X4(a1f[s][0], a1f[s][1], a1f[s][2], a1f[s][3],
                        sb + SM_X1 + abase + s * 32);
                LDSM_X4(a2f[s][0], a2f[s][1], a2f[s][2], a2f[s][3],
                        sb + SM_X2 + abase + s * 32);
            }
        }

        // --- wait W[k] ---
        if (buf == 0) { MBARRIER_WAIT_PARITY(mb + 8, wph0);  wph0 ^= 1; }
        else          { MBARRIER_WAIT_PARITY(mb + 16, wph1); wph1 ^= 1; }

        int n0 = t * 128;
        float p2v[2] = {0.f, 0.f};
        if (c == 0 && leader) {
            p2v[0] = g_P2[k * NTOK + n0 + r * 16 + g];
            p2v[1] = g_P2[k * NTOK + n0 + r * 16 + 8 + g];
        }

        uint32_t wbase = sb + SM_W + (uint32_t)buf * (2 * TILEB);
        uint32_t b1 = wbase + bbase;
        uint32_t b2 = b1 + TILEB;

        float dot[2] = {0, 0}, s1s[2] = {0, 0}, s2s[2] = {0, 0};

        #pragma unroll
        for (int ecg = 0; ecg < 4; ecg++) {
            float c1[2][4] = {{0, 0, 0, 0}, {0, 0, 0, 0}};
            float c2[2][4] = {{0, 0, 0, 0}, {0, 0, 0, 0}};
            #pragma unroll
            for (int s = 0; s < 8; s++) {
                #pragma unroll
                for (int ec = 0; ec < 2; ec++) {
                    uint32_t po = (uint32_t)((ecg * 2 + ec) * (8 * ROWB) + s * 32);
                    uint32_t u0, u1, v0, v1;
                    LDSM_X2(u0, u1, b1 + po);
                    LDSM_X2(v0, v1, b2 + po);
                    MMA_BF16(c1[ec], a1f[s], u0, u1);
                    MMA_BF16(c2[ec], a2f[s], v0, v1);
                }
            }
            #pragma unroll
            for (int ec = 0; ec < 2; ec++) {
                dot[0] = fmaf(c1[ec][0], c2[ec][0], dot[0]);
                dot[0] = fmaf(c1[ec][1], c2[ec][1], dot[0]);
                dot[1] = fmaf(c1[ec][2], c2[ec][2], dot[1]);
                dot[1] = fmaf(c1[ec][3], c2[ec][3], dot[1]);
                s1s[0] = fmaf(c1[ec][0], c1[ec][0], s1s[0]);
                s1s[0] = fmaf(c1[ec][1], c1[ec][1], s1s[0]);
                s1s[1] = fmaf(c1[ec][2], c1[ec][2], s1s[1]);
                s1s[1] = fmaf(c1[ec][3], c1[ec][3], s1s[1]);
                s2s[0] = fmaf(c2[ec][0], c2[ec][0], s2s[0]);
                s2s[0] = fmaf(c2[ec][1], c2[ec][1], s2s[0]);
                s2s[1] = fmaf(c2[ec][2], c2[ec][2], s2s[1]);
                s2s[1] = fmaf(c2[ec][3], c2[ec][3], s2s[1]);
            }
        }

        #pragma unroll
        for (int msk = 1; msk <= 2; msk <<= 1) {
            #pragma unroll
            for (int h = 0; h < 2; h++) {
                dot[h] += __shfl_xor_sync(0xFFFFFFFFu, dot[h], msk);
                s1s[h] += __shfl_xor_sync(0xFFFFFFFFu, s1s[h], msk);
                s2s[h] += __shfl_xor_sync(0xFFFFFFFFu, s2s[h], msk);
            }
        }

        if (c == 1 && leader) {
            #pragma unroll
            for (int h = 0; h < 2; h++) {
                int rr = r * 16 + h * 8 + g;
                red[rr * 3 + 0] = dot[h];
                red[rr * 3 + 1] = s1s[h];
                red[rr * 3 + 2] = s2s[h];
            }
        }
        __syncthreads();
        if (c == 0 && leader) {
            #pragma unroll
            for (int h = 0; h < 2; h++) {
                int rr = r * 16 + h * 8 + g;
                int n = n0 + rr;
                float D = dot[h] + red[rr * 3 + 0];
                float A = s1s[h] + red[rr * 3 + 1];
                float B = s2s[h] + red[rr * 3 + 2];
                float v = D / (fmaxf(sqrtf(A), 1e-8f) * fmaxf(sqrtf(B), 1e-8f)) + p2v[h];
                out[(size_t)n * KHEADS + k] = fmaxf(v, 0.f);
            }
        }
        __syncthreads();   // all reads of W buf + red done before buf refill

        // --- prefetch W for quantum q+2 into this buf ---
        if (tid == 0 && q + 2 < q1) {
            FENCE_PROXY_ASYNC();
            int kn = (q + 2) & 15;
            uint32_t wm = mb + 8 + (uint32_t)buf * 8;
            uint32_t wd = sb + SM_W + (uint32_t)buf * (2 * TILEB);
            MBARRIER_EXPECT_TX(wm, 2 * TILEB);
            CP_BULK(wd,         g_Wp1 + (size_t)kn * TILEB, TILEB, wm);
            CP_BULK(wd + TILEB, g_Wp2 + (size_t)kn * TILEB, TILEB, wm);
        }
    }
}

// ================= launch =================
extern "C" void kernel_launch(void* const* d_in, const int* in_sizes, int n_in,
                              void* d_out, int out_size) {
    const float* x1 = (const float*)d_in[0];
    const float* x2 = (const float*)d_in[1];
    const float* W1 = (const float*)d_in[2];
    const float* W2 = (const float*)d_in[3];
    const float* V  = (const float*)d_in[4];
    const float* b  = (const float*)d_in[5];
    float* out = (float*)d_out;

    k_prep<<<1536, 256>>>(x1, x2, W1, W2, V, b);

    cudaFuncSetAttribute(k_main, cudaFuncAttributeMaxDynamicSharedMemorySize, SM_TOT);
    k_main<<<NCTA, 512, SM_TOT>>>(out);
}